// round 6
// baseline (speedup 1.0000x reference)
#include <cuda_runtime.h>
#include <cuda_fp16.h>
#include <cuda_bf16.h>

// Problem constants
#define NB   32
#define RESO 256
#define KP   1024
#define FEPS 1e-6f
#define L2E  1.44269504088896340736f        // log2(e), T = 1
#define LN2F 0.69314718055994530942f

#define SPLITS       16                      // 256 thr = 16 jl x 16 splits
#define ITERS        (KP / SPLITS)           // 64 i per thread
#define COLS_PER_BLK 32                      // 16 jl x 2 cols/thread
#define LOSS_BLOCKS  (NB * (KP / COLS_PER_BLK))   // 1024

// Scratch (allocation-free rule: __device__ globals). Stored PRE-SCALED by L2E.
__device__ float2 g_src_c[NB * KP];
__device__ float2 g_trg_c[NB * KP];
__device__ float  g_loss_acc;
__device__ float  g_vis_acc;
__device__ int    g_vis_mode;                // 0 = uint8, 1 = int32, 2 = float32
__device__ unsigned int g_done = 0;

__device__ __forceinline__ float fsqrt_ap(float x) {
    float r; asm("sqrt.approx.f32 %0, %1;" : "=f"(r) : "f"(x)); return r;
}
__device__ __forceinline__ float frsq_ap(float x) {
    float r; asm("rsqrt.approx.f32 %0, %1;" : "=f"(r) : "f"(x)); return r;
}
__device__ __forceinline__ float flg2_ap(float x) {
    float r; asm("lg2.approx.f32 %0, %1;" : "=f"(r) : "f"(x)); return r;
}
// pack two f32 into f16x2 and take 2^x on both halves with ONE MUFU op
__device__ __forceinline__ __half2 ex2_pack(float a, float b) {
    unsigned int ru;
    asm("{\n\t.reg .b32 t;\n\t"
        "cvt.rn.f16x2.f32 t, %1, %2;\n\t"
        "ex2.approx.f16x2 %0, t;\n\t}"
        : "=r"(ru) : "f"(a), "f"(b));
    return *reinterpret_cast<__half2*>(&ru);
}
// -d (L2E-scaled): -d2 * rsqrt(d2); bias keeps rsq off 0
__device__ __forceinline__ float neg_dist(float2 s, float tnx, float tny) {
    float dx = s.x + tnx;
    float dy = s.y + tny;
    float d2 = fmaf(dy, dy, fmaf(dx, dx, 1e-30f));
    return (-d2) * frsq_ap(d2);
}

// Bilinear sample with zero padding, align_corners=True pixel coords.
__device__ __forceinline__ float2 bilin(const float2* __restrict__ flow, float x, float y) {
    float x0f = floorf(x), y0f = floorf(y);
    int   x0  = (int)x0f,  y0  = (int)y0f;
    float wx = x - x0f, wy = y - y0f;
    float ax = 0.f, ay = 0.f;
#pragma unroll
    for (int dy = 0; dy < 2; dy++) {
#pragma unroll
        for (int dx = 0; dx < 2; dx++) {
            int xi = x0 + dx, yi = y0 + dy;
            float w = (dx ? wx : 1.f - wx) * (dy ? wy : 1.f - wy);
            if (xi >= 0 && xi < RESO && yi >= 0 && yi < RESO) {
                float2 v = __ldg(&flow[yi * RESO + xi]);
                ax = fmaf(w, v.x, ax);
                ay = fmaf(w, v.y, ay);
            }
        }
    }
    return make_float2(ax, ay);
}

// ---------------------------------------------------------------------------
// Kernel 1 (fused): blocks 0..127 bilinear-sample (values pre-scaled by L2E);
// block 128 detects kp_vis storage dtype and zeroes accumulators.
// ---------------------------------------------------------------------------
__global__ void __launch_bounds__(256)
sample_detect_kernel(const float* __restrict__ src_flow,
                     const float* __restrict__ trg_flow,
                     const float* __restrict__ src_kp,
                     const float* __restrict__ trg_kp,
                     const unsigned char* __restrict__ kp_vis) {
    if (blockIdx.x == 128) {
        // --- detection: nonzero-byte pattern per i%4 over first NB*KP bytes ---
        __shared__ int cnt[4];
        int tid = threadIdx.x;
        if (tid < 4) cnt[tid] = 0;
        __syncthreads();
        const uint4* v4 = (const uint4*)kp_vis;      // 32768 bytes = 2048 uint4
        int c0 = 0, c1 = 0, c2 = 0, c3 = 0;
#pragma unroll
        for (int k = 0; k < 8; k++) {
            uint4 w = v4[tid + k * 256];
            unsigned int ws[4] = {w.x, w.y, w.z, w.w};
#pragma unroll
            for (int q = 0; q < 4; q++) {
                c0 += (ws[q] & 0x000000FFu) != 0;
                c1 += (ws[q] & 0x0000FF00u) != 0;
                c2 += (ws[q] & 0x00FF0000u) != 0;
                c3 += (ws[q] & 0xFF000000u) != 0;
            }
        }
        atomicAdd(&cnt[0], c0); atomicAdd(&cnt[1], c1);
        atomicAdd(&cnt[2], c2); atomicAdd(&cnt[3], c3);
        __syncthreads();
        if (tid == 0) {
            int r0 = cnt[0], r1 = cnt[1], r2 = cnt[2], r3 = cnt[3];
            int mode;
            if (r0 > 0 && r1 == 0 && r2 == 0 && r3 == 0)       mode = 1; // int32
            else if (r0 == 0 && r1 == 0 && (r2 > 0 || r3 > 0)) mode = 2; // float32
            else                                               mode = 0; // uint8
            g_vis_mode = mode;
            g_loss_acc = 0.f;
            g_vis_acc  = 0.f;
            g_done     = 0u;
        }
        return;
    }
    // --- sampling blocks ---
    int idx = blockIdx.x * blockDim.x + threadIdx.x;   // 0 .. 32767
    int n = idx >> 10;
    const float2* sf = (const float2*)src_flow + (size_t)n * RESO * RESO;
    const float2* tf = (const float2*)trg_flow + (size_t)n * RESO * RESO;
    float sx = src_kp[idx * 2 + 0], sy = src_kp[idx * 2 + 1];
    float tx = trg_kp[idx * 2 + 0], ty = trg_kp[idx * 2 + 1];
    float2 s = bilin(sf, sx, sy);
    float2 t = bilin(tf, tx, ty);
    g_src_c[idx] = make_float2(s.x * L2E, s.y * L2E);
    g_trg_c[idx] = make_float2(t.x * L2E, t.y * L2E);
}

// ---------------------------------------------------------------------------
// Kernel 2: per-column logsumexp + CE in base-2 units, fused finalize.
// grid = (KP/32, NB) = 1024 blocks; block = 256 = 16 jl x 16 splits.
// Each thread owns 2 columns (jl, jl+16): every LDS feeds two independent
// chains; f16x2 ex2 packs across the two columns at the same i.
// launch_bounds(256,4): up to 64 regs for deep software pipelining.
// ---------------------------------------------------------------------------
__global__ void __launch_bounds__(256, 4)
loss_kernel(const void* __restrict__ kp_vis,
            const float* __restrict__ kp_wt,
            float* __restrict__ out) {
    __shared__ float2 s_src[KP];                   // 8 KB (scaled by L2E)
    __shared__ float  s_part[SPLITS][COLS_PER_BLK];// 2 KB

    int n   = blockIdx.y;
    int jt  = blockIdx.x;
    int tid = threadIdx.x;

    const float2* src = g_src_c + n * KP;
    for (int i = tid; i < KP; i += 256) s_src[i] = src[i];
    __syncthreads();

    int jl    = tid & 15;                 // 0..15
    int split = tid >> 4;                 // 0..15
    int j0    = jt * COLS_PER_BLK + jl;   // first column
    int j1    = j0 + 16;                  // second column

    float2 t0 = g_trg_c[n * KP + j0];
    float2 t1 = g_trg_c[n * KP + j1];
    float tn0x = FEPS * L2E - t0.x, tn0y = FEPS * L2E - t0.y;
    float tn1x = FEPS * L2E - t1.x, tn1y = FEPS * L2E - t1.y;

    float S0 = 0.f, S1 = 0.f;
    int   i0 = split * ITERS;             // 64 i's per thread
    // 64 i = 8 flush groups x 8 i; lanes of hacc = (col0, col1)
#pragma unroll 2
    for (int g = 0; g < ITERS / 8; g++) {
        __half2 hacc = __float2half2_rn(0.f);
#pragma unroll
        for (int k = 0; k < 8; k++) {
            float2 s = s_src[i0 + g * 8 + k];
            float nd0 = neg_dist(s, tn0x, tn0y);
            float nd1 = neg_dist(s, tn1x, tn1y);
            hacc = __hadd2(hacc, ex2_pack(nd0, nd1));
        }
        float2 f = __half22float2(hacc);  // half-sums <= 8: low rounding error
        S0 += f.x;
        S1 += f.y;
    }
    s_part[split][jl]      = S0;
    s_part[split][jl + 16] = S1;
    __syncthreads();

    // warp 0: one column per lane (32 columns)
    if (tid < 32) {
        int col = tid;
        float Stot = 0.f;
#pragma unroll
        for (int k = 0; k < SPLITS; k++) Stot += s_part[k][col];

        int jg = jt * COLS_PER_BLK + col;
        float2 tc = g_trg_c[n * KP + jg];
        float tnx = FEPS * L2E - tc.x, tny = FEPS * L2E - tc.y;
        float2 sj = s_src[jg];
        float dxj = sj.x + tnx, dyj = sj.y + tny;
        float djj = fsqrt_ap(fmaf(dyj, dyj, dxj * dxj));   // exact diag (f32)
        // ce = LN2 * (lg2(S) + d'jj); forward d1 == d2 -> x2
        float ce = LN2F * (flg2_ap(Stot) + djj);
        int idx = n * KP + jg;
        int mode = g_vis_mode;
        float vv;
        if (mode == 0)      vv = ((const unsigned char*)kp_vis)[idx] ? 1.f : 0.f;
        else if (mode == 1) vv = ((const int*)kp_vis)[idx] ? 1.f : 0.f;
        else                vv = (((const float*)kp_vis)[idx] != 0.f) ? 1.f : 0.f;
        float contrib = 2.f * ce * vv * kp_wt[idx];

#pragma unroll
        for (int off = 16; off; off >>= 1) {
            contrib += __shfl_down_sync(0xffffffff, contrib, off);
            vv      += __shfl_down_sync(0xffffffff, vv, off);
        }
        if (tid == 0) {
            atomicAdd(&g_loss_acc, contrib);
            atomicAdd(&g_vis_acc, vv);
            __threadfence();
            unsigned int ticket = atomicAdd(&g_done, 1u);
            if (ticket == LOSS_BLOCKS - 1) {
                float num = atomicAdd(&g_loss_acc, 0.f);
                float den = atomicAdd(&g_vis_acc, 0.f);
                out[0] = num / den;
            }
        }
    }
}

extern "C" void kernel_launch(void* const* d_in, const int* in_sizes, int n_in,
                              void* d_out, int out_size) {
    const float* src_flow = (const float*)d_in[0];
    const float* trg_flow = (const float*)d_in[1];
    const float* src_kp   = (const float*)d_in[2];
    const float* trg_kp   = (const float*)d_in[3];
    const void*  kp_vis   = d_in[4];
    const float* kp_wt    = (const float*)d_in[5];
    float* out = (float*)d_out;

    sample_detect_kernel<<<129, 256>>>(src_flow, trg_flow, src_kp, trg_kp,
                                       (const unsigned char*)kp_vis);
    dim3 grid(KP / COLS_PER_BLK, NB);
    loss_kernel<<<grid, 256>>>(kp_vis, kp_wt, out);
}

// round 7
// speedup vs baseline: 1.3944x; 1.3944x over previous
#include <cuda_runtime.h>
#include <cuda_fp16.h>
#include <cuda_bf16.h>

// Problem constants
#define NB   32
#define RESO 256
#define KP   1024
#define FEPS 1e-6f
#define L2E  1.44269504088896340736f        // log2(e), T = 1
#define LN2F 0.69314718055994530942f

#define COLS_PER_BLK 32
#define SPLITS       8                       // 256 threads = 32 cols x 8 splits
#define ITERS        (KP / SPLITS)           // 128 pairs per thread
#define LOSS_BLOCKS  (NB * (KP / COLS_PER_BLK))   // 1024

// Scratch (allocation-free rule: __device__ globals). Stored PRE-SCALED by L2E.
__device__ float2 g_src_c[NB * KP];
__device__ float2 g_trg_c[NB * KP];
__device__ float  g_loss_acc;
__device__ float  g_vis_acc;
__device__ int    g_vis_mode;                // 0 = uint8, 1 = int32, 2 = float32
__device__ unsigned int g_done = 0;

__device__ __forceinline__ float fsqrt_ap(float x) {
    float r; asm("sqrt.approx.f32 %0, %1;" : "=f"(r) : "f"(x)); return r;
}
__device__ __forceinline__ float flg2_ap(float x) {
    float r; asm("lg2.approx.f32 %0, %1;" : "=f"(r) : "f"(x)); return r;
}
// pack two positive f32 distances, negate as f16x2 (one sign-flip LOP),
// then ONE MUFU ex2.f16x2 for both exponentials.
__device__ __forceinline__ __half2 ex2n_pack(float a, float b) {
    unsigned int ru;
    asm("{\n\t.reg .b32 t;\n\t"
        "cvt.rn.f16x2.f32 t, %1, %2;\n\t"
        "neg.f16x2 t, t;\n\t"
        "ex2.approx.f16x2 %0, t;\n\t}"
        : "=r"(ru) : "f"(a), "f"(b));
    return *reinterpret_cast<__half2*>(&ru);
}
// +d (L2E-scaled): sqrt(dx^2 + dy^2); d2 >= 0 by construction
__device__ __forceinline__ float pdist(float2 s, float tnx, float tny) {
    float dx = s.x + tnx;
    float dy = s.y + tny;
    return fsqrt_ap(fmaf(dy, dy, dx * dx));
}

// Bilinear sample with zero padding, align_corners=True pixel coords.
__device__ __forceinline__ float2 bilin(const float2* __restrict__ flow, float x, float y) {
    float x0f = floorf(x), y0f = floorf(y);
    int   x0  = (int)x0f,  y0  = (int)y0f;
    float wx = x - x0f, wy = y - y0f;
    float ax = 0.f, ay = 0.f;
#pragma unroll
    for (int dy = 0; dy < 2; dy++) {
#pragma unroll
        for (int dx = 0; dx < 2; dx++) {
            int xi = x0 + dx, yi = y0 + dy;
            float w = (dx ? wx : 1.f - wx) * (dy ? wy : 1.f - wy);
            if (xi >= 0 && xi < RESO && yi >= 0 && yi < RESO) {
                float2 v = __ldg(&flow[yi * RESO + xi]);
                ax = fmaf(w, v.x, ax);
                ay = fmaf(w, v.y, ay);
            }
        }
    }
    return make_float2(ax, ay);
}

// ---------------------------------------------------------------------------
// Kernel 1 (fused): blocks 0..127 bilinear-sample (values pre-scaled by L2E);
// block 128 detects kp_vis storage dtype and zeroes accumulators.
// ---------------------------------------------------------------------------
__global__ void __launch_bounds__(256)
sample_detect_kernel(const float* __restrict__ src_flow,
                     const float* __restrict__ trg_flow,
                     const float* __restrict__ src_kp,
                     const float* __restrict__ trg_kp,
                     const unsigned char* __restrict__ kp_vis) {
    if (blockIdx.x == 128) {
        // --- detection: nonzero-byte pattern per i%4 over first NB*KP bytes ---
        __shared__ int cnt[4];
        int tid = threadIdx.x;
        if (tid < 4) cnt[tid] = 0;
        __syncthreads();
        const uint4* v4 = (const uint4*)kp_vis;      // 32768 bytes = 2048 uint4
        int c0 = 0, c1 = 0, c2 = 0, c3 = 0;
#pragma unroll
        for (int k = 0; k < 8; k++) {
            uint4 w = v4[tid + k * 256];
            unsigned int ws[4] = {w.x, w.y, w.z, w.w};
#pragma unroll
            for (int q = 0; q < 4; q++) {
                c0 += (ws[q] & 0x000000FFu) != 0;
                c1 += (ws[q] & 0x0000FF00u) != 0;
                c2 += (ws[q] & 0x00FF0000u) != 0;
                c3 += (ws[q] & 0xFF000000u) != 0;
            }
        }
        atomicAdd(&cnt[0], c0); atomicAdd(&cnt[1], c1);
        atomicAdd(&cnt[2], c2); atomicAdd(&cnt[3], c3);
        __syncthreads();
        if (tid == 0) {
            int r0 = cnt[0], r1 = cnt[1], r2 = cnt[2], r3 = cnt[3];
            int mode;
            if (r0 > 0 && r1 == 0 && r2 == 0 && r3 == 0)       mode = 1; // int32
            else if (r0 == 0 && r1 == 0 && (r2 > 0 || r3 > 0)) mode = 2; // float32
            else                                               mode = 0; // uint8
            g_vis_mode = mode;
            g_loss_acc = 0.f;
            g_vis_acc  = 0.f;
            g_done     = 0u;
        }
        return;
    }
    // --- sampling blocks ---
    int idx = blockIdx.x * blockDim.x + threadIdx.x;   // 0 .. 32767
    int n = idx >> 10;
    const float2* sf = (const float2*)src_flow + (size_t)n * RESO * RESO;
    const float2* tf = (const float2*)trg_flow + (size_t)n * RESO * RESO;
    float sx = src_kp[idx * 2 + 0], sy = src_kp[idx * 2 + 1];
    float tx = trg_kp[idx * 2 + 0], ty = trg_kp[idx * 2 + 1];
    float2 s = bilin(sf, sx, sy);
    float2 t = bilin(tf, tx, ty);
    g_src_c[idx] = make_float2(s.x * L2E, s.y * L2E);
    g_trg_c[idx] = make_float2(t.x * L2E, t.y * L2E);
}

// ---------------------------------------------------------------------------
// Kernel 2: per-column logsumexp + CE in base-2 units, fused finalize.
// grid = (KP/32, NB) = 1024 blocks; block = 256 = 32 columns x 8 i-splits.
// Inner loop: 2 pairs/step, ONE MUFU ex2.f16x2; TWO independent half2
// accumulator chains per flush group for latency overlap.
// ---------------------------------------------------------------------------
__global__ void __launch_bounds__(256)
loss_kernel(const void* __restrict__ kp_vis,
            const float* __restrict__ kp_wt,
            float* __restrict__ out) {
    __shared__ float2 s_src[KP];      // 8 KB (scaled by L2E)
    __shared__ float  s_part[256];    // 1 KB

    int n   = blockIdx.y;
    int jt  = blockIdx.x;
    int tid = threadIdx.x;

    const float2* src = g_src_c + n * KP;
    for (int i = tid; i < KP; i += 256) s_src[i] = src[i];
    __syncthreads();

    int jl    = tid & (COLS_PER_BLK - 1);    // column within tile
    int split = tid >> 5;                    // 0..7 (warp id)
    int j     = jt * COLS_PER_BLK + jl;      // global column

    float2 t  = g_trg_c[n * KP + j];
    float tnx = FEPS * L2E - t.x;            // d = s - t + eps (scaled units)
    float tny = FEPS * L2E - t.y;

    float S  = 0.f;
    int   i0 = split * ITERS;
    // 128 pairs = 8 flush groups x (2 chains x 4 steps x 2 pairs)
#pragma unroll 2
    for (int g = 0; g < ITERS / 16; g++) {
        __half2 h0 = __float2half2_rn(0.f);
        __half2 h1 = __float2half2_rn(0.f);
#pragma unroll
        for (int k = 0; k < 4; k++) {
            int i = i0 + g * 16 + k * 4;
            float dA0 = pdist(s_src[i],     tnx, tny);
            float dA1 = pdist(s_src[i + 1], tnx, tny);
            float dB0 = pdist(s_src[i + 2], tnx, tny);
            float dB1 = pdist(s_src[i + 3], tnx, tny);
            h0 = __hadd2(h0, ex2n_pack(dA0, dA1));
            h1 = __hadd2(h1, ex2n_pack(dB0, dB1));
        }
        float2 f0 = __half22float2(h0);      // half-sums <= 4: low error
        float2 f1 = __half22float2(h1);
        S += (f0.x + f0.y) + (f1.x + f1.y);
    }
    s_part[tid] = S;
    __syncthreads();

    // warp 0 (split==0) owns the 32 columns of this tile
    if (split == 0) {
        float Stot = 0.f;
#pragma unroll
        for (int k = 0; k < SPLITS; k++) Stot += s_part[jl + k * COLS_PER_BLK];
        float2 sj  = s_src[j];
        float dxj  = sj.x + tnx;
        float dyj  = sj.y + tny;
        float djj  = fsqrt_ap(fmaf(dyj, dyj, dxj * dxj));   // exact diag (f32)
        // ce = ln(S) + dist = LN2 * (lg2(S) + d'jj); d1==d2 forward -> x2
        float ce = LN2F * (flg2_ap(Stot) + djj);
        int idx = n * KP + j;
        int mode = g_vis_mode;
        float vv;
        if (mode == 0)      vv = ((const unsigned char*)kp_vis)[idx] ? 1.f : 0.f;
        else if (mode == 1) vv = ((const int*)kp_vis)[idx] ? 1.f : 0.f;
        else                vv = (((const float*)kp_vis)[idx] != 0.f) ? 1.f : 0.f;
        float contrib = 2.f * ce * vv * kp_wt[idx];

#pragma unroll
        for (int off = 16; off; off >>= 1) {
            contrib += __shfl_down_sync(0xffffffff, contrib, off);
            vv      += __shfl_down_sync(0xffffffff, vv, off);
        }
        if (jl == 0) {
            atomicAdd(&g_loss_acc, contrib);
            atomicAdd(&g_vis_acc, vv);
            __threadfence();
            unsigned int ticket = atomicAdd(&g_done, 1u);
            if (ticket == LOSS_BLOCKS - 1) {
                float num = atomicAdd(&g_loss_acc, 0.f);
                float den = atomicAdd(&g_vis_acc, 0.f);
                out[0] = num / den;
            }
        }
    }
}

extern "C" void kernel_launch(void* const* d_in, const int* in_sizes, int n_in,
                              void* d_out, int out_size) {
    const float* src_flow = (const float*)d_in[0];
    const float* trg_flow = (const float*)d_in[1];
    const float* src_kp   = (const float*)d_in[2];
    const float* trg_kp   = (const float*)d_in[3];
    const void*  kp_vis   = d_in[4];
    const float* kp_wt    = (const float*)d_in[5];
    float* out = (float*)d_out;

    sample_detect_kernel<<<129, 256>>>(src_flow, trg_flow, src_kp, trg_kp,
                                       (const unsigned char*)kp_vis);
    dim3 grid(KP / COLS_PER_BLK, NB);
    loss_kernel<<<grid, 256>>>(kp_vis, kp_wt, out);
}